// round 2
// baseline (speedup 1.0000x reference)
#include <cuda_runtime.h>
#include <cstdint>
#include <cstddef>

// FastSeqProp: instance-norm(L=200) -> scale/shift -> softmax over C=4
// -> exact JAX threefry categorical sample (key 42, PARTITIONABLE threefry)
// -> straight-through -> pad with up/down pads to (N,4,600);
// outputs [softmax_padded, sampled_padded].

#define LEN   200
#define LPAD  600
#define NCH   4
#define EPSV  1e-5f
#define TINYF 1.17549435e-38f

// ---------------- Threefry-2x32, key = (0, 42) ----------------
__device__ __forceinline__ uint32_t rotl32(uint32_t x, int r) {
    return (x << r) | (x >> (32 - r));
}

__device__ __forceinline__ void tf_round(uint32_t& x0, uint32_t& x1, int r) {
    x0 += x1;
    x1 = rotl32(x1, r);
    x1 ^= x0;
}

__device__ __forceinline__ void threefry2x32_k42(uint32_t c0, uint32_t c1,
                                                 uint32_t& o0, uint32_t& o1) {
    const uint32_t ks0 = 0u;
    const uint32_t ks1 = 42u;
    const uint32_t ks2 = 0x1BD11BDAu ^ ks0 ^ ks1;  // 0x1BD11BF0
    uint32_t x0 = c0 + ks0;
    uint32_t x1 = c1 + ks1;

    tf_round(x0, x1, 13); tf_round(x0, x1, 15); tf_round(x0, x1, 26); tf_round(x0, x1, 6);
    x0 += ks1; x1 += ks2 + 1u;
    tf_round(x0, x1, 17); tf_round(x0, x1, 29); tf_round(x0, x1, 16); tf_round(x0, x1, 24);
    x0 += ks2; x1 += ks0 + 2u;
    tf_round(x0, x1, 13); tf_round(x0, x1, 15); tf_round(x0, x1, 26); tf_round(x0, x1, 6);
    x0 += ks0; x1 += ks1 + 3u;
    tf_round(x0, x1, 17); tf_round(x0, x1, 29); tf_round(x0, x1, 16); tf_round(x0, x1, 24);
    x0 += ks1; x1 += ks2 + 4u;
    tf_round(x0, x1, 13); tf_round(x0, x1, 15); tf_round(x0, x1, 26); tf_round(x0, x1, 6);
    x0 += ks2; x1 += ks0 + 5u;

    o0 = x0; o1 = x1;
}

// Partitionable threefry 32-bit random bits for flat index i (< 2^32):
// counter = (hi=0, lo=i), output = out0 ^ out1.
__device__ __forceinline__ uint32_t random_bits_partitionable(uint32_t idx) {
    uint32_t o0, o1;
    threefry2x32_k42(0u, idx, o0, o1);
    return o0 ^ o1;
}

// bits -> uniform in [tiny, 1) exactly like jax.random.uniform(minval=tiny, maxval=1)
__device__ __forceinline__ float bits_to_uniform(uint32_t bits) {
    float f = __uint_as_float((bits >> 9) | 0x3f800000u) - 1.0f;
    return fmaxf(f, TINYF);
}

// ---------------- Kernel ----------------
__global__ __launch_bounds__(256) void fastseqprop_kernel(
    const float* __restrict__ ts,    // (N,4,200)
    const float* __restrict__ scw,   // (N,4,1)
    const float* __restrict__ shw,   // (N,4,1)
    const float* __restrict__ up,    // (N,4,200)
    const float* __restrict__ dn,    // (N,4,200)
    float* __restrict__ out,         // (2,N,4,600) flattened
    size_t half_out)                 // N*4*600
{
    const int n    = blockIdx.x;
    const int t    = threadIdx.x;
    const int lane = t & 31;
    const int wid  = t >> 5;
    const bool act = (t < LEN);

    __shared__ float red[8][4];
    __shared__ float bc[4];

    const size_t in_base = (size_t)n * (NCH * LEN);

    // Load this position's 4 channel values (coalesced per channel row).
    float x0 = 0.f, x1 = 0.f, x2 = 0.f, x3 = 0.f;
    if (act) {
        x0 = ts[in_base + 0 * LEN + t];
        x1 = ts[in_base + 1 * LEN + t];
        x2 = ts[in_base + 2 * LEN + t];
        x3 = ts[in_base + 3 * LEN + t];
    }

    // pass 1: sums -> means
    {
        float v0 = x0, v1 = x1, v2 = x2, v3 = x3;
        #pragma unroll
        for (int o = 16; o > 0; o >>= 1) {
            v0 += __shfl_down_sync(0xffffffffu, v0, o);
            v1 += __shfl_down_sync(0xffffffffu, v1, o);
            v2 += __shfl_down_sync(0xffffffffu, v2, o);
            v3 += __shfl_down_sync(0xffffffffu, v3, o);
        }
        if (lane == 0) { red[wid][0] = v0; red[wid][1] = v1; red[wid][2] = v2; red[wid][3] = v3; }
        __syncthreads();
        if (t == 0) {
            float s0 = 0.f, s1 = 0.f, s2 = 0.f, s3 = 0.f;
            #pragma unroll
            for (int w = 0; w < 8; w++) { s0 += red[w][0]; s1 += red[w][1]; s2 += red[w][2]; s3 += red[w][3]; }
            bc[0] = s0; bc[1] = s1; bc[2] = s2; bc[3] = s3;
        }
        __syncthreads();
    }
    const float m0 = bc[0] / 200.0f;
    const float m1 = bc[1] / 200.0f;
    const float m2 = bc[2] / 200.0f;
    const float m3 = bc[3] / 200.0f;

    // centered values
    const float d0 = act ? (x0 - m0) : 0.f;
    const float d1 = act ? (x1 - m1) : 0.f;
    const float d2 = act ? (x2 - m2) : 0.f;
    const float d3 = act ? (x3 - m3) : 0.f;

    // pass 2: sum of squared deviations -> variance (biased, two-pass like jnp.var)
    {
        float v0 = d0 * d0, v1 = d1 * d1, v2 = d2 * d2, v3 = d3 * d3;
        #pragma unroll
        for (int o = 16; o > 0; o >>= 1) {
            v0 += __shfl_down_sync(0xffffffffu, v0, o);
            v1 += __shfl_down_sync(0xffffffffu, v1, o);
            v2 += __shfl_down_sync(0xffffffffu, v2, o);
            v3 += __shfl_down_sync(0xffffffffu, v3, o);
        }
        if (lane == 0) { red[wid][0] = v0; red[wid][1] = v1; red[wid][2] = v2; red[wid][3] = v3; }
        __syncthreads();
        if (t == 0) {
            float s0 = 0.f, s1 = 0.f, s2 = 0.f, s3 = 0.f;
            #pragma unroll
            for (int w = 0; w < 8; w++) { s0 += red[w][0]; s1 += red[w][1]; s2 += red[w][2]; s3 += red[w][3]; }
            bc[0] = s0; bc[1] = s1; bc[2] = s2; bc[3] = s3;
        }
        __syncthreads();
    }
    const float var0 = bc[0] / 200.0f;
    const float var1 = bc[1] / 200.0f;
    const float var2 = bc[2] / 200.0f;
    const float var3 = bc[3] / 200.0f;

    if (!act) return;

    const float r0 = rsqrtf(var0 + EPSV);
    const float r1 = rsqrtf(var1 + EPSV);
    const float r2 = rsqrtf(var2 + EPSV);
    const float r3 = rsqrtf(var3 + EPSV);

    const size_t wbase = (size_t)n * NCH;
    float sc[4];
    sc[0] = (d0 * r0) * scw[wbase + 0] + shw[wbase + 0];
    sc[1] = (d1 * r1) * scw[wbase + 1] + shw[wbase + 1];
    sc[2] = (d2 * r2) * scw[wbase + 2] + shw[wbase + 2];
    sc[3] = (d3 * r3) * scw[wbase + 3] + shw[wbase + 3];

    // softmax over channels
    const float mx  = fmaxf(fmaxf(sc[0], sc[1]), fmaxf(sc[2], sc[3]));
    float sh[4], ex[4];
    #pragma unroll
    for (int c = 0; c < 4; c++) { sh[c] = sc[c] - mx; ex[c] = expf(sh[c]); }
    const float ssum = ((ex[0] + ex[1]) + ex[2]) + ex[3];
    float soft[4];
    #pragma unroll
    for (int c = 0; c < 4; c++) soft[c] = ex[c] / ssum;
    const float lse = logf(ssum);

    // ---- gumbel noise: partitionable threefry, flat index in (N, L, 4) ----
    const uint32_t gb = 4u * (uint32_t)(n * LEN + t);
    float best = -1e30f;
    int   besti = 0;
    #pragma unroll
    for (int c = 0; c < 4; c++) {
        const uint32_t bits = random_bits_partitionable(gb + (uint32_t)c);
        const float u = bits_to_uniform(bits);
        const float g = -logf(-logf(u));
        // logits = log_softmax = shifted - lse ; gumbel + logits, first max wins
        const float v = g + (sh[c] - lse);
        if (v > best) { best = v; besti = c; }
    }

    // ---- write outputs: out0 = pad(softmax), out1 = pad(sampled) ----
    float* out0 = out;
    float* out1 = out + half_out;
    const size_t obase = (size_t)n * (NCH * LPAD);

    #pragma unroll
    for (int c = 0; c < 4; c++) {
        const float u_v = up[in_base + c * LEN + t];
        const float d_v = dn[in_base + c * LEN + t];
        const float s_v = soft[c];
        const float oh  = (c == besti) ? 1.0f : 0.0f;
        const float samp = (oh - s_v) + s_v;   // straight-through, f32 op order as ref

        const size_t row = obase + (size_t)c * LPAD;
        out0[row + t]             = u_v;
        out0[row + LEN + t]       = s_v;
        out0[row + 2 * LEN + t]   = d_v;
        out1[row + t]             = u_v;
        out1[row + LEN + t]       = samp;
        out1[row + 2 * LEN + t]   = d_v;
    }
}

extern "C" void kernel_launch(void* const* d_in, const int* in_sizes, int n_in,
                              void* d_out, int out_size) {
    const float* ts  = (const float*)d_in[0];
    const float* scw = (const float*)d_in[1];
    const float* shw = (const float*)d_in[2];
    const float* up  = (const float*)d_in[3];
    const float* dn  = (const float*)d_in[4];
    float* out = (float*)d_out;

    const int nseq = in_sizes[0] / (NCH * LEN);      // 8192
    const size_t half_out = (size_t)out_size / 2;    // N*4*600

    fastseqprop_kernel<<<nseq, 256>>>(ts, scw, shw, up, dn, out, half_out);
}

// round 3
// speedup vs baseline: 1.0330x; 1.0330x over previous
#include <cuda_runtime.h>
#include <cstdint>

// FastSeqProp: instance-norm(L=200) -> scale/shift -> softmax over C=4
// -> exact JAX threefry categorical (key 42, partitionable) -> straight-through
// -> pad to (N,4,600); outputs [softmax_padded, sampled_padded].
//
// All floating-point math is kept bit-identical to the validated R2 kernel
// (zero argmax flips). This round only restructures WORK DISTRIBUTION:
//  - threefry densely spread over all 256 threads (25 warp-blocks vs 28)
//  - global loads issued before the threefry ALU stretch (latency overlap)
//  - 32-bit index arithmetic

#define LEN   200
#define LPAD  600
#define NCH   4
#define EPSV  1e-5f
#define TINYF 1.17549435e-38f

__device__ __forceinline__ uint32_t rotl32(uint32_t x, int r) {
    return (x << r) | (x >> (32 - r));
}

__device__ __forceinline__ void tf_round(uint32_t& x0, uint32_t& x1, int r) {
    x0 += x1;
    x1 = rotl32(x1, r);
    x1 ^= x0;
}

__device__ __forceinline__ uint32_t tf_bits_k42(uint32_t idx) {
    // threefry2x32, key=(0,42), counter=(0, idx); out = x0 ^ x1 (partitionable path)
    const uint32_t ks0 = 0u;
    const uint32_t ks1 = 42u;
    const uint32_t ks2 = 0x1BD11BDAu ^ ks0 ^ ks1;
    uint32_t x0 = 0u + ks0;
    uint32_t x1 = idx + ks1;

    tf_round(x0, x1, 13); tf_round(x0, x1, 15); tf_round(x0, x1, 26); tf_round(x0, x1, 6);
    x0 += ks1; x1 += ks2 + 1u;
    tf_round(x0, x1, 17); tf_round(x0, x1, 29); tf_round(x0, x1, 16); tf_round(x0, x1, 24);
    x0 += ks2; x1 += ks0 + 2u;
    tf_round(x0, x1, 13); tf_round(x0, x1, 15); tf_round(x0, x1, 26); tf_round(x0, x1, 6);
    x0 += ks0; x1 += ks1 + 3u;
    tf_round(x0, x1, 17); tf_round(x0, x1, 29); tf_round(x0, x1, 16); tf_round(x0, x1, 24);
    x0 += ks1; x1 += ks2 + 4u;
    tf_round(x0, x1, 13); tf_round(x0, x1, 15); tf_round(x0, x1, 26); tf_round(x0, x1, 6);
    x0 += ks2; x1 += ks0 + 5u;

    return x0 ^ x1;
}

__device__ __forceinline__ float gumbel_from_bits(uint32_t bits) {
    float f = __uint_as_float((bits >> 9) | 0x3f800000u) - 1.0f;
    float u = fmaxf(f, TINYF);
    return -logf(-logf(u));   // accurate logf: bit-identical to R2
}

__global__ __launch_bounds__(256) void fastseqprop_kernel(
    const float* __restrict__ ts,    // (N,4,200)
    const float* __restrict__ scw,   // (N,4,1)
    const float* __restrict__ shw,   // (N,4,1)
    const float* __restrict__ up,    // (N,4,200)
    const float* __restrict__ dn,    // (N,4,200)
    float* __restrict__ out,         // (2,N,4,600) flattened
    uint32_t half_out)               // N*4*600
{
    const uint32_t n    = blockIdx.x;
    const uint32_t t    = threadIdx.x;
    const uint32_t lane = t & 31u;
    const uint32_t wid  = t >> 5;
    const bool act = (t < LEN);

    __shared__ float red[8][4];
    __shared__ float bc[4];
    __shared__ float sgum[NCH * LEN];   // gumbel values, layout [c*200 + l]

    const uint32_t in_base = n * (NCH * LEN);
    const uint32_t wbase   = n * NCH;

    // ---- issue ALL global loads up front (hidden under the threefry stretch) ----
    float x0 = 0.f, x1 = 0.f, x2 = 0.f, x3 = 0.f;
    float upv[4], dnv[4];
    if (act) {
        x0 = ts[in_base + 0 * LEN + t];
        x1 = ts[in_base + 1 * LEN + t];
        x2 = ts[in_base + 2 * LEN + t];
        x3 = ts[in_base + 3 * LEN + t];
        #pragma unroll
        for (int c = 0; c < 4; c++) {
            upv[c] = up[in_base + (uint32_t)c * LEN + t];
            dnv[c] = dn[in_base + (uint32_t)c * LEN + t];
        }
    }
    float scv[4], shv[4];
    if (act) {
        #pragma unroll
        for (int c = 0; c < 4; c++) {
            scv[c] = scw[wbase + (uint32_t)c];
            shv[c] = shw[wbase + (uint32_t)c];
        }
    }

    // ---- dense threefry: 800 draws over 256 threads (3 each, +1 for t<32) ----
    // flat gumbel index for (n,l,c) in shape (N,L,4): gbase + (l*4 + c)
    {
        const uint32_t gbase = n * (LEN * NCH);
        uint32_t j0 = t;
        uint32_t j1 = t + 256u;
        uint32_t j2 = t + 512u;
        uint32_t b0 = tf_bits_k42(gbase + j0);
        uint32_t b1 = tf_bits_k42(gbase + j1);
        uint32_t b2 = tf_bits_k42(gbase + j2);
        sgum[(j0 & 3u) * LEN + (j0 >> 2)] = gumbel_from_bits(b0);
        sgum[(j1 & 3u) * LEN + (j1 >> 2)] = gumbel_from_bits(b1);
        sgum[(j2 & 3u) * LEN + (j2 >> 2)] = gumbel_from_bits(b2);
        if (t < 32u) {
            uint32_t j3 = t + 768u;
            uint32_t b3 = tf_bits_k42(gbase + j3);
            sgum[(j3 & 3u) * LEN + (j3 >> 2)] = gumbel_from_bits(b3);
        }
    }

    // ---- pass 1: sums -> means (identical structure/order to R2) ----
    {
        float v0 = x0, v1 = x1, v2 = x2, v3 = x3;
        #pragma unroll
        for (int o = 16; o > 0; o >>= 1) {
            v0 += __shfl_down_sync(0xffffffffu, v0, o);
            v1 += __shfl_down_sync(0xffffffffu, v1, o);
            v2 += __shfl_down_sync(0xffffffffu, v2, o);
            v3 += __shfl_down_sync(0xffffffffu, v3, o);
        }
        if (lane == 0) { red[wid][0] = v0; red[wid][1] = v1; red[wid][2] = v2; red[wid][3] = v3; }
        __syncthreads();
        if (t == 0) {
            float s0 = 0.f, s1 = 0.f, s2 = 0.f, s3 = 0.f;
            #pragma unroll
            for (int w = 0; w < 8; w++) { s0 += red[w][0]; s1 += red[w][1]; s2 += red[w][2]; s3 += red[w][3]; }
            bc[0] = s0; bc[1] = s1; bc[2] = s2; bc[3] = s3;
        }
        __syncthreads();
    }
    const float m0 = bc[0] / 200.0f;
    const float m1 = bc[1] / 200.0f;
    const float m2 = bc[2] / 200.0f;
    const float m3 = bc[3] / 200.0f;

    const float d0 = act ? (x0 - m0) : 0.f;
    const float d1 = act ? (x1 - m1) : 0.f;
    const float d2 = act ? (x2 - m2) : 0.f;
    const float d3 = act ? (x3 - m3) : 0.f;

    // ---- pass 2: centered sum of squares -> biased variance ----
    {
        float v0 = d0 * d0, v1 = d1 * d1, v2 = d2 * d2, v3 = d3 * d3;
        #pragma unroll
        for (int o = 16; o > 0; o >>= 1) {
            v0 += __shfl_down_sync(0xffffffffu, v0, o);
            v1 += __shfl_down_sync(0xffffffffu, v1, o);
            v2 += __shfl_down_sync(0xffffffffu, v2, o);
            v3 += __shfl_down_sync(0xffffffffu, v3, o);
        }
        if (lane == 0) { red[wid][0] = v0; red[wid][1] = v1; red[wid][2] = v2; red[wid][3] = v3; }
        __syncthreads();
        if (t == 0) {
            float s0 = 0.f, s1 = 0.f, s2 = 0.f, s3 = 0.f;
            #pragma unroll
            for (int w = 0; w < 8; w++) { s0 += red[w][0]; s1 += red[w][1]; s2 += red[w][2]; s3 += red[w][3]; }
            bc[0] = s0; bc[1] = s1; bc[2] = s2; bc[3] = s3;
        }
        __syncthreads();
    }
    const float var0 = bc[0] / 200.0f;
    const float var1 = bc[1] / 200.0f;
    const float var2 = bc[2] / 200.0f;
    const float var3 = bc[3] / 200.0f;

    if (!act) return;

    const float r0 = rsqrtf(var0 + EPSV);
    const float r1 = rsqrtf(var1 + EPSV);
    const float r2 = rsqrtf(var2 + EPSV);
    const float r3 = rsqrtf(var3 + EPSV);

    float sc[4];
    sc[0] = (d0 * r0) * scv[0] + shv[0];
    sc[1] = (d1 * r1) * scv[1] + shv[1];
    sc[2] = (d2 * r2) * scv[2] + shv[2];
    sc[3] = (d3 * r3) * scv[3] + shv[3];

    // softmax over channels (accurate expf/logf, identical to R2)
    const float mx  = fmaxf(fmaxf(sc[0], sc[1]), fmaxf(sc[2], sc[3]));
    float sh[4], ex[4];
    #pragma unroll
    for (int c = 0; c < 4; c++) { sh[c] = sc[c] - mx; ex[c] = expf(sh[c]); }
    const float ssum = ((ex[0] + ex[1]) + ex[2]) + ex[3];
    float soft[4];
    #pragma unroll
    for (int c = 0; c < 4; c++) soft[c] = ex[c] / ssum;
    const float lse = logf(ssum);

    // ---- argmax over gumbel + log_softmax (first max wins) ----
    float best = -1e30f;
    int   besti = 0;
    #pragma unroll
    for (int c = 0; c < 4; c++) {
        const float g = sgum[(uint32_t)c * LEN + t];
        const float v = g + (sh[c] - lse);
        if (v > best) { best = v; besti = c; }
    }

    // ---- write outputs ----
    float* out0 = out;
    float* out1 = out + half_out;
    const uint32_t obase = n * (NCH * LPAD);

    #pragma unroll
    for (int c = 0; c < 4; c++) {
        const float s_v = soft[c];
        const float oh  = (c == besti) ? 1.0f : 0.0f;
        const float samp = (oh - s_v) + s_v;

        const uint32_t row = obase + (uint32_t)c * LPAD;
        out0[row + t]           = upv[c];
        out0[row + LEN + t]     = s_v;
        out0[row + 2 * LEN + t] = dnv[c];
        out1[row + t]           = upv[c];
        out1[row + LEN + t]     = samp;
        out1[row + 2 * LEN + t] = dnv[c];
    }
}

extern "C" void kernel_launch(void* const* d_in, const int* in_sizes, int n_in,
                              void* d_out, int out_size) {
    const float* ts  = (const float*)d_in[0];
    const float* scw = (const float*)d_in[1];
    const float* shw = (const float*)d_in[2];
    const float* up  = (const float*)d_in[3];
    const float* dn  = (const float*)d_in[4];
    float* out = (float*)d_out;

    const int nseq = in_sizes[0] / (NCH * LEN);          // 8192
    const uint32_t half_out = (uint32_t)(out_size / 2);  // N*4*600

    fastseqprop_kernel<<<nseq, 256>>>(ts, scw, shw, up, dn, out, half_out);
}